// round 14
// baseline (speedup 1.0000x reference)
#include <cuda_runtime.h>
#include <cuda_bf16.h>

// QuantumCBOW: B=16384, S=10, DIM=8, TRIL=36.
// R14: 4 lanes/element (65536 threads, 2048 warps = 3.46/SMSP) with R5's
// proven one-sided Jacobi core, but redundancy removed:
//  - densities split 3/3/3/3 (11 total; sigma only on lanes 2,3)
//  - ONE Cholesky per lane (lanes 0,1: ctx->C; lanes 2,3: sigma->S)
//  - factors distributed by two width-4 broadcasts
// Chip work ~6.3M warp-instrs (-31% vs R12) at 2x the warps/SMSP.

#define QC_DIM  8
#define QC_TRIL 36
#define QC_S    10

__device__ __forceinline__ constexpr int sidx(int i, int j) { return i * (i + 1) / 2 + j; }

// density(row) -> dst[36] (lower-tri), weight 1. (trace-normalized, eps'd)
__device__ __forceinline__ void dens_compute(const float* __restrict__ row, float* dst) {
    float L[QC_TRIL];
    const float4* r4 = reinterpret_cast<const float4*>(row);  // 36*4B rows, 16B aligned
#pragma unroll
    for (int v = 0; v < 9; v++) {
        float4 t = r4[v];
        L[4 * v + 0] = t.x; L[4 * v + 1] = t.y;
        L[4 * v + 2] = t.z; L[4 * v + 3] = t.w;
    }
#pragma unroll
    for (int i = 0; i < QC_DIM; i++) {
        const int d = sidx(i, i);
        L[d] = fmaxf(L[d], 1e-4f);
    }
    float tr = 0.f;
#pragma unroll
    for (int i = 0; i < QC_TRIL; i++) tr = fmaf(L[i], L[i], tr);
    const float inv = __fdividef(1.0f, tr + 1.7e-5f);
#pragma unroll
    for (int i = 0; i < QC_DIM; i++) {
#pragma unroll
        for (int j = 0; j <= i; j++) {
            float s = 0.f;
#pragma unroll
            for (int k = 0; k <= j; k++)
                s = fmaf(L[sidx(i, k)], L[sidx(j, k)], s);
            if (i == j) s += 2e-6f;  // eps + corr
            dst[sidx(i, j)] = s * inv;
        }
    }
}

// acc += wgt * density(row)
__device__ __forceinline__ void add_density(const float* __restrict__ row, float* acc, float wgt) {
    float tmp[QC_TRIL];
    dens_compute(row, tmp);
#pragma unroll
    for (int i = 0; i < QC_TRIL; i++) acc[i] = fmaf(wgt, tmp[i], acc[i]);
}

// Lower-tri element of Cb with compile-time zero padding.
#define CEL(k, j) (((k) >= (j)) ? Cb[(k) * ((k) + 1) / 2 + (j)] : 0.0f)

// One-sided rotation of own column against partner snapshot (R5-validated:
// both lanes see (n, pn) swapped -> dd flips sign -> consistent updates).
#define OS_ROT(colx, px, nx, pnx) do {                                         \
    float g = 0.f;                                                             \
    _Pragma("unroll")                                                          \
    for (int k = 0; k < QC_DIM; k++) g = fmaf(colx[k], px[k], g);              \
    const float dd = (pnx) - (nx);                                             \
    const float a2 = 2.0f * g;                                                 \
    const float vv = fmaf(dd, dd, fmaf(a2, a2, 1e-30f));                       \
    const float u  = vv * rsqrtf(vv);                                          \
    const float t  = __fdividef(a2 * copysignf(1.0f, dd), fabsf(dd) + u);      \
    const float c  = rsqrtf(fmaf(t, t, 1.0f));                                 \
    const float s  = t * c;                                                    \
    _Pragma("unroll")                                                          \
    for (int k = 0; k < QC_DIM; k++)                                           \
        colx[k] = fmaf(c, colx[k], -s * px[k]);                                \
    nx = fmaf(-t, g, nx);                                                      \
} while (0)

// Local rotation of the pair (ca, cb) owned by this lane (R5-validated).
#define OS_LOCAL() do {                                                        \
    float g = 0.f;                                                             \
    _Pragma("unroll")                                                          \
    for (int k = 0; k < QC_DIM; k++) g = fmaf(ca[k], cb[k], g);                \
    const float dd = nb - na;                                                  \
    const float a2 = 2.0f * g;                                                 \
    const float vv = fmaf(dd, dd, fmaf(a2, a2, 1e-30f));                       \
    const float u  = vv * rsqrtf(vv);                                          \
    const float t  = __fdividef(a2 * copysignf(1.0f, dd), fabsf(dd) + u);      \
    const float c  = rsqrtf(fmaf(t, t, 1.0f));                                 \
    const float s  = t * c;                                                    \
    _Pragma("unroll")                                                          \
    for (int k = 0; k < QC_DIM; k++) {                                         \
        const float x = ca[k], y = cb[k];                                      \
        ca[k] = fmaf(c, x, -s * y);                                            \
        cb[k] = fmaf(s, x,  c * y);                                            \
    }                                                                          \
    na = fmaf(-t, g, na);                                                      \
    nb = fmaf( t, g, nb);                                                      \
} while (0)

// Cross round with lane l^m (m in {1,2,3} stays inside the 4-lane group).
// CROSSED=0: (ca<->p.ca, cb<->p.cb); CROSSED=1: (ca<->p.cb, cb<->p.ca).
#define OS_CROSS(m, CROSSED) do {                                              \
    float pa[QC_DIM], pb[QC_DIM];                                              \
    _Pragma("unroll")                                                          \
    for (int k = 0; k < QC_DIM; k++) {                                         \
        pa[k] = __shfl_xor_sync(0xffffffffu, (CROSSED) ? cb[k] : ca[k], (m));  \
        pb[k] = __shfl_xor_sync(0xffffffffu, (CROSSED) ? ca[k] : cb[k], (m));  \
    }                                                                          \
    float pna = __shfl_xor_sync(0xffffffffu, (CROSSED) ? nb : na, (m));        \
    float pnb = __shfl_xor_sync(0xffffffffu, (CROSSED) ? na : nb, (m));        \
    OS_ROT(ca, pa, na, pna);                                                   \
    OS_ROT(cb, pb, nb, pnb);                                                   \
} while (0)

__global__ void __launch_bounds__(64, 7)
qcbow_kernel(const int* __restrict__ contexts,
             const int* __restrict__ targets,
             const float* __restrict__ emb,
             float* __restrict__ out,
             int B) {
    const int gt = blockIdx.x * 64 + threadIdx.x;
    int e = gt >> 2;
    const int l = gt & 3;              // lane within 4-lane group
    const bool valid = (e < B);
    if (!valid) e = 0;                 // clamp (keep shfl groups intact)

    // ---- token assignment: lanes 0,1 -> {l, l+4, l+8}; lanes 2,3 -> {l, l+4} + target
    const bool hasT3 = (l < 2);
    const int tok0 = contexts[e * QC_S + l];
    const int tok1 = contexts[e * QC_S + l + 4];
    const int tok2 = hasT3 ? contexts[e * QC_S + l + 8] : targets[e];

    // ---- two ctx densities ----
    float ctxp[QC_TRIL];
#pragma unroll
    for (int i = 0; i < QC_TRIL; i++) ctxp[i] = 0.f;
    const float m0 = (tok0 != 0) ? 1.0f : 0.0f;
    const float m1 = (tok1 != 0) ? 1.0f : 0.0f;
    float cnt = m0 + m1;
    add_density(emb + (long)tok0 * QC_TRIL, ctxp, m0);
    add_density(emb + (long)tok1 * QC_TRIL, ctxp, m1);

    // ---- third density: ctx token (lanes 0,1) or sigma (lanes 2,3) ----
    const float mc2 = hasT3 ? ((tok2 != 0) ? 1.0f : 0.0f) : 0.0f;  // ctx weight
    const float ms2 = hasT3 ? 0.0f : 1.0f;                          // sigma weight
    cnt += mc2;
    float sigm[QC_TRIL];
    {
        float tmp[QC_TRIL];
        dens_compute(emb + (long)tok2 * QC_TRIL, tmp);
#pragma unroll
        for (int i = 0; i < QC_TRIL; i++) {
            ctxp[i] = fmaf(mc2, tmp[i], ctxp[i]);
            sigm[i] = ms2 * tmp[i];
        }
    }

    // ---- butterfly: full ctx + cnt across the 4-lane group ----
#pragma unroll
    for (int i = 0; i < QC_TRIL; i++) ctxp[i] += __shfl_xor_sync(0xffffffffu, ctxp[i], 1);
    cnt += __shfl_xor_sync(0xffffffffu, cnt, 1);
#pragma unroll
    for (int i = 0; i < QC_TRIL; i++) ctxp[i] += __shfl_xor_sync(0xffffffffu, ctxp[i], 2);
    cnt += __shfl_xor_sync(0xffffffffu, cnt, 2);
    const float ic = __fdividef(1.0f, cnt);  // cnt==0 -> inf, matches ref 0/0

    // ---- my Cholesky target: lanes 0,1 -> ctx/cnt + 1e-6 I; lanes 2,3 -> sigma ----
    float mat[QC_TRIL];
#pragma unroll
    for (int i = 0; i < QC_TRIL; i++) {
        const float cv = ctxp[i] * ic;
        mat[i] = hasT3 ? cv : sigm[i];
    }
    const float dadd = hasT3 ? 1e-6f : 0.0f;
#pragma unroll
    for (int d = 0; d < QC_DIM; d++) mat[sidx(d, d)] += dadd;

    // ---- in-place Cholesky of mat (uniform code, per-lane data) ----
#pragma unroll
    for (int j = 0; j < QC_DIM; j++) {
        float d = mat[sidx(j, j)];
#pragma unroll
        for (int k = 0; k < j; k++) d = fmaf(-mat[sidx(j, k)], mat[sidx(j, k)], d);
        d = fmaxf(d, 1e-20f);
        const float icjj = rsqrtf(d);
        mat[sidx(j, j)] = d * icjj;
#pragma unroll
        for (int i = j + 1; i < QC_DIM; i++) {
            float v = mat[sidx(i, j)];
#pragma unroll
            for (int k = 0; k < j; k++) v = fmaf(-mat[sidx(i, k)], mat[sidx(j, k)], v);
            mat[sidx(i, j)] = v * icjj;
        }
    }
    // lanes 0,1: mat = C (CC^T = ctx+1e-6I); lanes 2,3: mat = S (SS^T = sigma)

    // ---- distribute factors: C from lane 0, S from lane 2 (width-4 bcast) ----
    float Cb[QC_TRIL], Sb[QC_TRIL];
#pragma unroll
    for (int i = 0; i < QC_TRIL; i++) {
        Cb[i] = __shfl_sync(0xffffffffu, mat[i], 0, 4);
        Sb[i] = __shfl_sync(0xffffffffu, mat[i], 2, 4);
    }

    // ---- my two columns of A = S^T C  (cols l and l+4) ----
    float Cl[QC_DIM], Cm[QC_DIM];
#pragma unroll
    for (int k = 0; k < QC_DIM; k++) {
        Cl[k] = (l == 0) ? CEL(k, 0) : (l == 1) ? CEL(k, 1) : (l == 2) ? CEL(k, 2) : CEL(k, 3);
        Cm[k] = (l == 0) ? CEL(k, 4) : (l == 1) ? CEL(k, 5) : (l == 2) ? CEL(k, 6) : CEL(k, 7);
    }
    float ca[QC_DIM], cb[QC_DIM];
#pragma unroll
    for (int i = 0; i < QC_DIM; i++) {
        float sa = 0.f, sb = 0.f;
#pragma unroll
        for (int k = i; k < QC_DIM; k++) {
            const float sv = Sb[sidx(k, i)];
            sa = fmaf(sv, Cl[k], sa);
            sb = fmaf(sv, Cm[k], sb);
        }
        ca[i] = sa; cb[i] = sb;
    }

    // ---- one-sided Jacobi, 3 sweeps x (1 local + 6 cross) rounds ----
    float na, nb;
#pragma unroll 1
    for (int sweep = 0; sweep < 3; sweep++) {
        na = 0.f; nb = 0.f;
#pragma unroll
        for (int k = 0; k < QC_DIM; k++) {
            na = fmaf(ca[k], ca[k], na);
            nb = fmaf(cb[k], cb[k], nb);
        }
        OS_LOCAL();            // (l, l+4)
        OS_CROSS(1, 0);
        OS_CROSS(1, 1);
        OS_CROSS(2, 0);
        OS_CROSS(2, 1);
        OS_CROSS(3, 0);
        OS_CROSS(3, 1);
    }

    // ---- f = sum sqrt(colnorm^2 + eps); reduce over 4 lanes ----
    {
        float s0 = 0.f, s1 = 0.f;
#pragma unroll
        for (int k = 0; k < QC_DIM; k++) {
            s0 = fmaf(ca[k], ca[k], s0);
            s1 = fmaf(cb[k], cb[k], s1);
        }
        const float x0 = s0 + 1e-6f;
        const float x1 = s1 + 1e-6f;
        float p = fmaf(x0, rsqrtf(x0), x1 * rsqrtf(x1));
        p += __shfl_xor_sync(0xffffffffu, p, 1);
        p += __shfl_xor_sync(0xffffffffu, p, 2);
        if (valid && l == 0) {
            float f = fminf(p, 1.0f);
            f = fmaxf(f, 1e-8f);
            out[e] = -logf(f);
        }
    }
}

extern "C" void kernel_launch(void* const* d_in, const int* in_sizes, int n_in,
                              void* d_out, int out_size) {
    const int*   contexts = (const int*)d_in[0];   // [B, 10] int32
    const int*   targets  = (const int*)d_in[1];   // [B] int32
    const float* emb      = (const float*)d_in[2]; // [V, 36] float32
    float*       out      = (float*)d_out;         // [B] float32
    const int B = in_sizes[1];                     // 16384
    const int threads = 64;
    const int blocks = (4 * B + threads - 1) / threads;   // 1024 blocks
    qcbow_kernel<<<blocks, threads>>>(contexts, targets, emb, out, B);
}

// round 15
// speedup vs baseline: 1.9423x; 1.9423x over previous
#include <cuda_runtime.h>
#include <cuda_bf16.h>

// QuantumCBOW: B=16384, S=10, DIM=8, TRIL=36.
// R15 = R12 (best: 2 lanes/element, split Cholesky, one-sided Jacobi, 16.86us)
// + two mechanical levers:
//  * Jacobi columns packed as f32x2 (sm_103a fma.rn.f32x2 / mul.rn.f32x2 via
//    PTX): rotation updates halved, dots 8->5 instrs. Same per-element
//    rounding as scalar FMA.
//  * 64-thread blocks (512 blocks) for even SM load (R12's 256x128 left a
//    2:1 per-SM imbalance). __launch_bounds__(64,4) -> 256-reg cap, no spills.

#define QC_DIM  8
#define QC_TRIL 36
#define QC_S    10

typedef unsigned long long u64p;

__device__ __forceinline__ constexpr int sidx(int i, int j) { return i * (i + 1) / 2 + j; }

#define F2PK(d, lo, hi)  asm("mov.b64 %0, {%1, %2};" : "=l"(d) : "f"(lo), "f"(hi))
#define F2UP(lo, hi, s)  asm("mov.b64 {%0, %1}, %2;" : "=f"(lo), "=f"(hi) : "l"(s))
#define FMA2(d, a, b, c) asm("fma.rn.f32x2 %0, %1, %2, %3;" : "=l"(d) : "l"(a), "l"(b), "l"(c))
#define MUL2(d, a, b)    asm("mul.rn.f32x2 %0, %1, %2;" : "=l"(d) : "l"(a), "l"(b))

// Packed dot of two 4xu64p (8-float) vectors -> scalar.
#define PDOT(res, X, Y) do {                                                   \
    u64p _acc = 0ull;                                                          \
    _Pragma("unroll")                                                          \
    for (int _k = 0; _k < 4; _k++) FMA2(_acc, X[_k], Y[_k], _acc);             \
    float _lo, _hi; F2UP(_lo, _hi, _acc);                                      \
    res = _lo + _hi;                                                           \
} while (0)

// Accumulate wgt * normalized-density(row) into acc[36] (lower-tri storage).
__device__ __forceinline__ void add_density(const float* __restrict__ row, float* acc, float wgt) {
    float L[QC_TRIL];
    const float4* r4 = reinterpret_cast<const float4*>(row);  // 36*4B rows, 16B aligned
#pragma unroll
    for (int v = 0; v < 9; v++) {
        float4 t = r4[v];
        L[4 * v + 0] = t.x; L[4 * v + 1] = t.y;
        L[4 * v + 2] = t.z; L[4 * v + 3] = t.w;
    }
#pragma unroll
    for (int i = 0; i < QC_DIM; i++) {
        const int d = sidx(i, i);
        L[d] = fmaxf(L[d], 1e-4f);
    }
    float tr = 0.f;
#pragma unroll
    for (int i = 0; i < QC_TRIL; i++) tr = fmaf(L[i], L[i], tr);
    const float inv = wgt * __fdividef(1.0f, tr + 1.7e-5f);
#pragma unroll
    for (int i = 0; i < QC_DIM; i++) {
#pragma unroll
        for (int j = 0; j <= i; j++) {
            float s = 0.f;
#pragma unroll
            for (int k = 0; k <= j; k++)
                s = fmaf(L[sidx(i, k)], L[sidx(j, k)], s);
            if (i == j) s += 2e-6f;  // eps + corr
            acc[sidx(i, j)] = fmaf(s, inv, acc[sidx(i, j)]);
        }
    }
}

// One-sided rotation of packed own column X against partner snapshot P.
// Both lanes of a pair see (n, pn) swapped -> dd flips sign -> consistent
// updates (R5/R12-validated formula).
#define OS_ROT(X, P, nx, pnx) do {                                             \
    float g; PDOT(g, X, P);                                                    \
    const float dd = (pnx) - (nx);                                             \
    const float a2 = 2.0f * g;                                                 \
    const float vv = fmaf(dd, dd, fmaf(a2, a2, 1e-30f));                       \
    const float u  = vv * rsqrtf(vv);                                          \
    const float t  = __fdividef(a2 * copysignf(1.0f, dd), fabsf(dd) + u);      \
    const float c  = rsqrtf(fmaf(t, t, 1.0f));                                 \
    const float s  = t * c;                                                    \
    u64p _cc, _ns; const float _m = -s;                                        \
    F2PK(_cc, c, c); F2PK(_ns, _m, _m);                                        \
    _Pragma("unroll")                                                          \
    for (int _k = 0; _k < 4; _k++) {                                           \
        u64p _t; MUL2(_t, _ns, P[_k]); FMA2(X[_k], _cc, X[_k], _t);            \
    }                                                                          \
    nx = fmaf(-t, g, nx);                                                      \
} while (0)

// Local rotation of two packed own columns X, Y (full update).
#define OS_LOCAL(X, Y, nx, ny) do {                                            \
    float g; PDOT(g, X, Y);                                                    \
    const float dd = (ny) - (nx);                                              \
    const float a2 = 2.0f * g;                                                 \
    const float vv = fmaf(dd, dd, fmaf(a2, a2, 1e-30f));                       \
    const float u  = vv * rsqrtf(vv);                                          \
    const float t  = __fdividef(a2 * copysignf(1.0f, dd), fabsf(dd) + u);      \
    const float c  = rsqrtf(fmaf(t, t, 1.0f));                                 \
    const float s  = t * c;                                                    \
    u64p _cc, _ss, _ns; const float _m = -s;                                   \
    F2PK(_cc, c, c); F2PK(_ss, s, s); F2PK(_ns, _m, _m);                       \
    _Pragma("unroll")                                                          \
    for (int _k = 0; _k < 4; _k++) {                                           \
        const u64p _x = X[_k], _y = Y[_k];                                     \
        u64p _t1, _t2;                                                         \
        MUL2(_t1, _ns, _y); FMA2(X[_k], _cc, _x, _t1);                         \
        MUL2(_t2, _cc, _y); FMA2(Y[_k], _ss, _x, _t2);                         \
    }                                                                          \
    nx = fmaf(-t, g, nx);                                                      \
    ny = fmaf( t, g, ny);                                                      \
} while (0)

// Cross round x: own col c pairs with partner col c^x (lane xor 1). Snapshot
// all partner cols + norms BEFORE rotating (state consistency).
#define XROUND(x) do {                                                         \
    u64p p0[4], p1[4], p2[4], p3[4];                                           \
    _Pragma("unroll")                                                          \
    for (int _k = 0; _k < 4; _k++) {                                           \
        p0[_k] = __shfl_xor_sync(0xffffffffu, A[0 ^ (x)][_k], 1);              \
        p1[_k] = __shfl_xor_sync(0xffffffffu, A[1 ^ (x)][_k], 1);              \
        p2[_k] = __shfl_xor_sync(0xffffffffu, A[2 ^ (x)][_k], 1);              \
        p3[_k] = __shfl_xor_sync(0xffffffffu, A[3 ^ (x)][_k], 1);              \
    }                                                                          \
    const float q0 = __shfl_xor_sync(0xffffffffu, n[0 ^ (x)], 1);              \
    const float q1 = __shfl_xor_sync(0xffffffffu, n[1 ^ (x)], 1);              \
    const float q2 = __shfl_xor_sync(0xffffffffu, n[2 ^ (x)], 1);              \
    const float q3 = __shfl_xor_sync(0xffffffffu, n[3 ^ (x)], 1);              \
    OS_ROT(A[0], p0, n[0], q0);                                                \
    OS_ROT(A[1], p1, n[1], q1);                                                \
    OS_ROT(A[2], p2, n[2], q2);                                                \
    OS_ROT(A[3], p3, n[3], q3);                                                \
} while (0)

__global__ void __launch_bounds__(64, 4)
qcbow_kernel(const int* __restrict__ contexts,
             const int* __restrict__ targets,
             const float* __restrict__ emb,
             float* __restrict__ out,
             int B) {
    const int gt = blockIdx.x * 64 + threadIdx.x;
    const int e = gt >> 1;
    const int h = gt & 1;
    if (e >= B) return;   // 2B % 64 == 0 -> no partial pairs/warps

    // ---- token ids (row is 8B-aligned: 10 ints = 5 x int2) ----
    int toks[QC_S];
    {
        const int2* c2 = reinterpret_cast<const int2*>(contexts + e * QC_S);
#pragma unroll
        for (int v = 0; v < 5; v++) {
            const int2 t = c2[v];
            toks[2 * v] = t.x; toks[2 * v + 1] = t.y;
        }
    }
    const int tgt = targets[e];

    // ---- sigma density (both lanes; same row -> L1 broadcast) ----
    float sigm[QC_TRIL];
#pragma unroll
    for (int i = 0; i < QC_TRIL; i++) sigm[i] = 0.f;
    add_density(emb + (long)tgt * QC_TRIL, sigm, 1.0f);

    // ---- 5 context densities for this lane: tokens {2k + h} ----
    float ctxp[QC_TRIL];
#pragma unroll
    for (int i = 0; i < QC_TRIL; i++) ctxp[i] = 0.f;
    float cnt = 0.f;
#pragma unroll
    for (int k = 0; k < 5; k++) {
        const int tok = toks[2 * k + h];
        const float m = (tok != 0) ? 1.0f : 0.0f;
        cnt += m;
        add_density(emb + (long)tok * QC_TRIL, ctxp, m);
    }

    // ---- butterfly: full ctx + cnt across the lane pair ----
    cnt += __shfl_xor_sync(0xffffffffu, cnt, 1);
#pragma unroll
    for (int i = 0; i < QC_TRIL; i++)
        ctxp[i] += __shfl_xor_sync(0xffffffffu, ctxp[i], 1);
    const float ic = __fdividef(1.0f, cnt);  // cnt==0 -> inf, matches ref 0/0

    // ---- my Cholesky target: h0 -> ctx/cnt + 1e-6 I, h1 -> sigma ----
    float mat[QC_TRIL];
#pragma unroll
    for (int i = 0; i < QC_TRIL; i++) {
        const float cv = ctxp[i] * ic;
        mat[i] = h ? sigm[i] : cv;
    }
    const float dadd = h ? 0.0f : 1e-6f;
#pragma unroll
    for (int d = 0; d < QC_DIM; d++) mat[sidx(d, d)] += dadd;

    // ---- in-place Cholesky of mat (uniform code, per-lane data) ----
#pragma unroll
    for (int j = 0; j < QC_DIM; j++) {
        float d = mat[sidx(j, j)];
#pragma unroll
        for (int k = 0; k < j; k++) d = fmaf(-mat[sidx(j, k)], mat[sidx(j, k)], d);
        d = fmaxf(d, 1e-20f);
        const float icjj = rsqrtf(d);
        mat[sidx(j, j)] = d * icjj;
#pragma unroll
        for (int i = j + 1; i < QC_DIM; i++) {
            float v = mat[sidx(i, j)];
#pragma unroll
            for (int k = 0; k < j; k++) v = fmaf(-mat[sidx(i, k)], mat[sidx(j, k)], v);
            mat[sidx(i, j)] = v * icjj;
        }
    }
    // h0: mat = C (CC^T = ctx+1e-6I); h1: mat = S (SS^T = sigma)

    // ---- factor exchange + materialize S, C ----
    float S[QC_TRIL], C[QC_TRIL];
#pragma unroll
    for (int i = 0; i < QC_TRIL; i++) {
        const float o = __shfl_xor_sync(0xffffffffu, mat[i], 1);
        S[i] = h ? mat[i] : o;
        C[i] = h ? o : mat[i];
    }

    // ---- my 4 columns of A = S^T C (cols 4h..4h+3); pack into f32x2 ----
    u64p A[4][4];
#pragma unroll
    for (int jj = 0; jj < 4; jj++) {
        float Cc[QC_DIM];   // C[k][4h+jj], zero-padded k<col (compile-time idx + SEL)
#pragma unroll
        for (int k = 0; k < QC_DIM; k++) {
            const float v0 = (k >= jj)     ? C[(k >= jj)     ? sidx(k, jj)     : 0] : 0.f;
            const float v1 = (k >= jj + 4) ? C[(k >= jj + 4) ? sidx(k, jj + 4) : 0] : 0.f;
            Cc[k] = h ? v1 : v0;
        }
        float av[QC_DIM];
#pragma unroll
        for (int i = 0; i < QC_DIM; i++) {
            float s = 0.f;
#pragma unroll
            for (int k = i; k < QC_DIM; k++)
                s = fmaf(S[sidx(k, i)], Cc[k], s);
            av[i] = s;
        }
#pragma unroll
        for (int k = 0; k < 4; k++) F2PK(A[jj][k], av[2 * k], av[2 * k + 1]);
    }

    // ---- one-sided Jacobi (packed): 3 sweeps x (6 local + 4 cross rounds) ----
    float n[4];
#pragma unroll 1
    for (int sweep = 0; sweep < 3; sweep++) {
        // fresh norms each sweep
#pragma unroll
        for (int jj = 0; jj < 4; jj++) PDOT(n[jj], A[jj], A[jj]);
        OS_LOCAL(A[0], A[1], n[0], n[1]); OS_LOCAL(A[2], A[3], n[2], n[3]);
        OS_LOCAL(A[0], A[2], n[0], n[2]); OS_LOCAL(A[1], A[3], n[1], n[3]);
        OS_LOCAL(A[0], A[3], n[0], n[3]); OS_LOCAL(A[1], A[2], n[1], n[2]);
        XROUND(0); XROUND(1); XROUND(2); XROUND(3);
    }

    // ---- f = sum sqrt(colnorm^2 + eps) over all 8 cols ----
    float p = 0.f;
#pragma unroll
    for (int jj = 0; jj < 4; jj++) {
        float s; PDOT(s, A[jj], A[jj]);
        const float x = s + 1e-6f;
        p = fmaf(x, rsqrtf(x), p);   // sqrt(x) = x*rsqrt(x)
    }
    p += __shfl_xor_sync(0xffffffffu, p, 1);
    if (h == 0) {
        float f = fminf(p, 1.0f);
        f = fmaxf(f, 1e-8f);
        out[e] = -logf(f);
    }
}

extern "C" void kernel_launch(void* const* d_in, const int* in_sizes, int n_in,
                              void* d_out, int out_size) {
    const int*   contexts = (const int*)d_in[0];   // [B, 10] int32
    const int*   targets  = (const int*)d_in[1];   // [B] int32
    const float* emb      = (const float*)d_in[2]; // [V, 36] float32
    float*       out      = (float*)d_out;         // [B] float32
    const int B = in_sizes[1];                     // 16384
    const int threads = 64;
    const int blocks = (2 * B + threads - 1) / threads;   // 512 blocks
    qcbow_kernel<<<blocks, threads>>>(contexts, targets, emb, out, B);
}